// round 1
// baseline (speedup 1.0000x reference)
#include <cuda_runtime.h>
#include <cstdint>

// MetaDynamics: out[p] = sum_h hgt[h] * exp(-0.5 * sum_d (cen[h,d]-col[p,d])^2 / wdt[h,d]^2)
// H=16384 hills, P=4096 points, D=8 CVs.
//
// Strategy: FMA-bound problem (all data fits in L2). Use Blackwell packed f32x2
// math (2 points per register pair), 4 points per thread. Hill data is stored
// DUPLICATED ({v,v} in 8 bytes) in shared memory so LDS.128 broadcast loads give
// ready-packed operands with zero pack MOVs in the inner loop.
// exp(-0.5*e) == exp2(sum_d r^2 * iv2[h,d]) with iv2 = -0.5*log2(e)/wdt^2,
// so the inner loop is pure add/mul/fma + one ex2.approx per pair.

#define N_HILLS   16384
#define N_POINTS  4096
#define N_CV      8

#define CHUNK_H   32                       // hills per block
#define NCHUNKS   (N_HILLS / CHUNK_H)      // 512
#define THREADS   256
#define PTS_PER_THREAD 4
#define PTS_PER_BLOCK  (THREADS * PTS_PER_THREAD)   // 1024
#define PTILES    (N_POINTS / PTS_PER_BLOCK)        // 4

typedef unsigned long long u64;

// Partial sums: [NCHUNKS][N_POINTS] = 8 MB device-global scratch (no allocs).
__device__ __align__(16) float g_part[NCHUNKS * N_POINTS];

// ---- packed f32x2 helpers (sm_100+) ----
__device__ __forceinline__ u64 f2_add(u64 a, u64 b) {
    u64 d; asm("add.rn.f32x2 %0, %1, %2;" : "=l"(d) : "l"(a), "l"(b)); return d;
}
__device__ __forceinline__ u64 f2_mul(u64 a, u64 b) {
    u64 d; asm("mul.rn.f32x2 %0, %1, %2;" : "=l"(d) : "l"(a), "l"(b)); return d;
}
__device__ __forceinline__ u64 f2_fma(u64 a, u64 b, u64 c) {
    u64 d; asm("fma.rn.f32x2 %0, %1, %2, %3;" : "=l"(d) : "l"(a), "l"(b), "l"(c)); return d;
}
__device__ __forceinline__ float ex2f(float x) {
    float y; asm("ex2.approx.f32 %0, %1;" : "=f"(y) : "f"(x)); return y;
}
__device__ __forceinline__ u64 pack2(float lo, float hi) {
    u64 d;
    asm("mov.b64 %0, {%1, %2};" : "=l"(d) : "r"(__float_as_uint(lo)), "r"(__float_as_uint(hi)));
    return d;
}
__device__ __forceinline__ float f2_lo(u64 a) { return __uint_as_float((unsigned)(a)); }
__device__ __forceinline__ float f2_hi(u64 a) { return __uint_as_float((unsigned)(a >> 32)); }
__device__ __forceinline__ u64 dup_bits(float v) {
    u64 b = (u64)__float_as_uint(v);
    return b | (b << 32);
}

__global__ void __launch_bounds__(THREADS)
metadyn_main(const float* __restrict__ col,
             const float* __restrict__ cen,
             const float* __restrict__ wdt,
             const float* __restrict__ hgt)
{
    // Hill tile cached in shared memory, every value duplicated into both
    // halves of an 8-byte word so inner-loop LDS gives packed f32x2 operands.
    __shared__ __align__(16) u64 s_cen[CHUNK_H * N_CV];   // 2 KB
    __shared__ __align__(16) u64 s_iv [CHUNK_H * N_CV];   // 2 KB  (-0.5*log2e / wdt^2)
    __shared__ __align__(16) u64 s_hgt[CHUNK_H];          // 256 B

    const int   tid = threadIdx.x;
    const int   h0  = blockIdx.y * CHUNK_H;
    const float NEG_HALF_LOG2E = -0.72134752044448170f;

    // Fill: 32 hills * 8 dims = 256 elems, exactly one per thread.
    {
        const int h = tid >> 3;           // tid / 8
        const int d = tid & 7;            // tid % 8
        const int g = (h0 + h) * N_CV + d;
        float c  = cen[g];
        float w  = wdt[g];
        float iv = NEG_HALF_LOG2E / (w * w);
        s_cen[tid] = dup_bits(c);
        s_iv [tid] = dup_bits(iv);
        if (d == 0) s_hgt[h] = dup_bits(hgt[h0 + h]);
    }
    __syncthreads();

    // Each thread owns 4 consecutive points; keep -col packed in registers.
    const int p0 = blockIdx.x * PTS_PER_BLOCK + tid * PTS_PER_THREAD;
    u64 ncol[2][N_CV];
    #pragma unroll
    for (int j = 0; j < 2; ++j) {
        const float* a = col + (p0 + 2 * j) * N_CV;       // point 2j
        const float* b = col + (p0 + 2 * j + 1) * N_CV;   // point 2j+1
        float4 a0 = *(const float4*)(a);
        float4 a1 = *(const float4*)(a + 4);
        float4 b0 = *(const float4*)(b);
        float4 b1 = *(const float4*)(b + 4);
        ncol[j][0] = pack2(-a0.x, -b0.x);
        ncol[j][1] = pack2(-a0.y, -b0.y);
        ncol[j][2] = pack2(-a0.z, -b0.z);
        ncol[j][3] = pack2(-a0.w, -b0.w);
        ncol[j][4] = pack2(-a1.x, -b1.x);
        ncol[j][5] = pack2(-a1.y, -b1.y);
        ncol[j][6] = pack2(-a1.z, -b1.z);
        ncol[j][7] = pack2(-a1.w, -b1.w);
    }

    u64 out0 = 0ULL, out1 = 0ULL;   // packed {0.0f, 0.0f}

    #pragma unroll 4
    for (int h = 0; h < CHUNK_H; ++h) {
        const u64* ch = &s_cen[h * N_CV];
        const u64* vh = &s_iv [h * N_CV];
        u64 acc0 = 0ULL, acc1 = 0ULL;
        #pragma unroll
        for (int dd = 0; dd < 4; ++dd) {
            // LDS.128: two dims of duplicated cen / iv at once (broadcast, conflict-free)
            ulonglong2 c2 = *(const ulonglong2*)&ch[2 * dd];
            ulonglong2 v2 = *(const ulonglong2*)&vh[2 * dd];
            {
                u64 r0 = f2_add(c2.x, ncol[0][2 * dd]);
                acc0 = f2_fma(r0, f2_mul(r0, v2.x), acc0);
                u64 r1 = f2_add(c2.x, ncol[1][2 * dd]);
                acc1 = f2_fma(r1, f2_mul(r1, v2.x), acc1);
            }
            {
                u64 r0 = f2_add(c2.y, ncol[0][2 * dd + 1]);
                acc0 = f2_fma(r0, f2_mul(r0, v2.y), acc0);
                u64 r1 = f2_add(c2.y, ncol[1][2 * dd + 1]);
                acc1 = f2_fma(r1, f2_mul(r1, v2.y), acc1);
            }
        }
        // acc already equals -0.5*log2e * e  -> exp(-0.5 e) = 2^acc
        u64 hg = s_hgt[h];
        u64 E0 = pack2(ex2f(f2_lo(acc0)), ex2f(f2_hi(acc0)));
        u64 E1 = pack2(ex2f(f2_lo(acc1)), ex2f(f2_hi(acc1)));
        out0 = f2_fma(hg, E0, out0);
        out1 = f2_fma(hg, E1, out1);
    }

    float4 r;
    r.x = f2_lo(out0); r.y = f2_hi(out0);
    r.z = f2_lo(out1); r.w = f2_hi(out1);
    *(float4*)&g_part[blockIdx.y * N_POINTS + p0] = r;
}

__global__ void __launch_bounds__(256)
metadyn_reduce(float* __restrict__ out)
{
    const int p = blockIdx.x * blockDim.x + threadIdx.x;   // 0..4095
    float s0 = 0.f, s1 = 0.f, s2 = 0.f, s3 = 0.f;
    #pragma unroll 4
    for (int c = 0; c < NCHUNKS; c += 4) {
        s0 += g_part[(c + 0) * N_POINTS + p];
        s1 += g_part[(c + 1) * N_POINTS + p];
        s2 += g_part[(c + 2) * N_POINTS + p];
        s3 += g_part[(c + 3) * N_POINTS + p];
    }
    out[p] = (s0 + s1) + (s2 + s3);
}

extern "C" void kernel_launch(void* const* d_in, const int* in_sizes, int n_in,
                              void* d_out, int out_size)
{
    const float* col = (const float*)d_in[0];
    const float* cen = (const float*)d_in[1];
    const float* wdt = (const float*)d_in[2];
    const float* hgt = (const float*)d_in[3];
    float* out = (float*)d_out;

    dim3 grid(PTILES, NCHUNKS);
    metadyn_main<<<grid, THREADS>>>(col, cen, wdt, hgt);
    metadyn_reduce<<<N_POINTS / 256, 256>>>(out);
}

// round 3
// speedup vs baseline: 1.3345x; 1.3345x over previous
#include <cuda_runtime.h>
#include <cstdint>

// MetaDynamics: out[p] = sum_h hgt[h] * exp(-0.5 * sum_d (cen[h,d]-col[p,d])^2 / wdt[h,d]^2)
// H=16384, P=4096, D=8.
//
// Strategy (R1 resubmit after infra failure):
//  * Expand the quadratic: iv*(cen-col)^2 = iv*cen^2 + b*col + c*col^2,
//    b = -2*iv*cen, c = iv, iv = -0.5*log2e/wdt^2. Per-hill A' = sum_d iv*cen_d^2 + log2(hgt).
//    Inner loop per dim: t = fma(c, col, b); acc = fma(t, col, acc) -> 2 FMAs/dim (was 3),
//    hgt folded into the exponent (exp2), killing the per-hill height FMA.
//  * Packed f32x2 math (2 points/register pair), 4 points/thread, hill data duplicated
//    {v,v} in smem so LDS.128 broadcast yields packed operands.
//  * CHUNK_H=64 -> 4 MB partial buffer; parallel tree reduce (128 blocks).

#define N_HILLS   16384
#define N_POINTS  4096
#define N_CV      8

#define CHUNK_H   64                        // hills per block
#define NCHUNKS   (N_HILLS / CHUNK_H)       // 256
#define THREADS   256
#define PTS_PER_THREAD 4
#define PTS_PER_BLOCK  (THREADS * PTS_PER_THREAD)   // 1024
#define PTILES    (N_POINTS / PTS_PER_BLOCK)        // 4

typedef unsigned long long u64;

// Partial sums: [NCHUNKS][N_POINTS] = 4 MB device-global scratch.
__device__ __align__(16) float g_part[NCHUNKS * N_POINTS];

// ---- packed f32x2 helpers (sm_100+) ----
__device__ __forceinline__ u64 f2_add(u64 a, u64 b) {
    u64 d; asm("add.rn.f32x2 %0, %1, %2;" : "=l"(d) : "l"(a), "l"(b)); return d;
}
__device__ __forceinline__ u64 f2_fma(u64 a, u64 b, u64 c) {
    u64 d; asm("fma.rn.f32x2 %0, %1, %2, %3;" : "=l"(d) : "l"(a), "l"(b), "l"(c)); return d;
}
__device__ __forceinline__ float ex2f(float x) {
    float y; asm("ex2.approx.f32 %0, %1;" : "=f"(y) : "f"(x)); return y;
}
__device__ __forceinline__ float lg2f(float x) {
    float y; asm("lg2.approx.f32 %0, %1;" : "=f"(y) : "f"(x)); return y;
}
__device__ __forceinline__ u64 pack2(float lo, float hi) {
    u64 d;
    asm("mov.b64 %0, {%1, %2};" : "=l"(d) : "r"(__float_as_uint(lo)), "r"(__float_as_uint(hi)));
    return d;
}
__device__ __forceinline__ float f2_lo(u64 a) { return __uint_as_float((unsigned)(a)); }
__device__ __forceinline__ float f2_hi(u64 a) { return __uint_as_float((unsigned)(a >> 32)); }
__device__ __forceinline__ u64 dup_bits(float v) {
    u64 b = (u64)__float_as_uint(v);
    return b | (b << 32);
}

__global__ void __launch_bounds__(THREADS)
metadyn_main(const float* __restrict__ col,
             const float* __restrict__ cen,
             const float* __restrict__ wdt,
             const float* __restrict__ hgt)
{
    // Per-hill coefficients, duplicated into both halves of u64 for packed math.
    __shared__ __align__(16) u64 s_b[CHUNK_H * N_CV];   // -2*iv*cen      (4 KB)
    __shared__ __align__(16) u64 s_c[CHUNK_H * N_CV];   // iv             (4 KB)
    __shared__ __align__(16) u64 s_A[CHUNK_H];          // sum iv*cen^2 + log2(hgt)
    __shared__ float s_ivc2[CHUNK_H * N_CV];            // iv*cen^2 staging (2 KB)

    const int   tid = threadIdx.x;
    const int   h0  = blockIdx.y * CHUNK_H;
    const float NEG_HALF_LOG2E = -0.72134752044448170f;

    // Fill: all 256 threads do 2 (hill,dim) pairs each (512 total).
    #pragma unroll
    for (int k = 0; k < 2; ++k) {
        const int e = tid + k * THREADS;     // 0..511
        const int h = e >> 3;                // hill within chunk
        const int d = e & 7;
        const int g = (h0 + h) * N_CV + d;
        float c  = cen[g];
        float w  = wdt[g];
        float iv = NEG_HALF_LOG2E / (w * w);
        s_b[e]    = dup_bits(-2.0f * iv * c);
        s_c[e]    = dup_bits(iv);
        s_ivc2[e] = iv * c * c;
    }
    __syncthreads();
    if (tid < CHUNK_H) {
        float A = lg2f(hgt[h0 + tid]);
        #pragma unroll
        for (int d = 0; d < N_CV; ++d) A += s_ivc2[tid * N_CV + d];
        s_A[tid] = dup_bits(A);
    }
    __syncthreads();

    // Each thread owns 4 consecutive points, packed two-by-two.
    const int p0 = blockIdx.x * PTS_PER_BLOCK + tid * PTS_PER_THREAD;
    u64 cp[2][N_CV];
    #pragma unroll
    for (int j = 0; j < 2; ++j) {
        const float* a = col + (p0 + 2 * j) * N_CV;
        const float* b = col + (p0 + 2 * j + 1) * N_CV;
        float4 a0 = *(const float4*)(a);
        float4 a1 = *(const float4*)(a + 4);
        float4 b0 = *(const float4*)(b);
        float4 b1 = *(const float4*)(b + 4);
        cp[j][0] = pack2(a0.x, b0.x);
        cp[j][1] = pack2(a0.y, b0.y);
        cp[j][2] = pack2(a0.z, b0.z);
        cp[j][3] = pack2(a0.w, b0.w);
        cp[j][4] = pack2(a1.x, b1.x);
        cp[j][5] = pack2(a1.y, b1.y);
        cp[j][6] = pack2(a1.z, b1.z);
        cp[j][7] = pack2(a1.w, b1.w);
    }

    u64 out0 = 0ULL, out1 = 0ULL;   // packed {0.0f, 0.0f}

    #pragma unroll 2
    for (int h = 0; h < CHUNK_H; ++h) {
        const u64* bh = &s_b[h * N_CV];
        const u64* ch = &s_c[h * N_CV];
        const u64 Ah  = s_A[h];
        // Two dependency chains per packed pair (dims split even/odd position).
        u64 aA0 = Ah,   aB0 = 0ULL;
        u64 aA1 = Ah,   aB1 = 0ULL;
        #pragma unroll
        for (int dd = 0; dd < 4; ++dd) {
            ulonglong2 b2 = *(const ulonglong2*)&bh[2 * dd];
            ulonglong2 c2 = *(const ulonglong2*)&ch[2 * dd];
            {   // dim 2dd -> chain A
                u64 t0 = f2_fma(c2.x, cp[0][2 * dd], b2.x);
                aA0 = f2_fma(t0, cp[0][2 * dd], aA0);
                u64 t1 = f2_fma(c2.x, cp[1][2 * dd], b2.x);
                aA1 = f2_fma(t1, cp[1][2 * dd], aA1);
            }
            {   // dim 2dd+1 -> chain B
                u64 t0 = f2_fma(c2.y, cp[0][2 * dd + 1], b2.y);
                aB0 = f2_fma(t0, cp[0][2 * dd + 1], aB0);
                u64 t1 = f2_fma(c2.y, cp[1][2 * dd + 1], b2.y);
                aB1 = f2_fma(t1, cp[1][2 * dd + 1], aB1);
            }
        }
        u64 e0 = f2_add(aA0, aB0);
        u64 e1 = f2_add(aA1, aB1);
        // 2^(acc) already includes hgt (log2(hgt) folded into A)
        u64 E0 = pack2(ex2f(f2_lo(e0)), ex2f(f2_hi(e0)));
        u64 E1 = pack2(ex2f(f2_lo(e1)), ex2f(f2_hi(e1)));
        out0 = f2_add(out0, E0);
        out1 = f2_add(out1, E1);
    }

    float4 r;
    r.x = f2_lo(out0); r.y = f2_hi(out0);
    r.z = f2_lo(out1); r.w = f2_hi(out1);
    *(float4*)&g_part[blockIdx.y * N_POINTS + p0] = r;
}

// Parallel reduce: 128 blocks x 256 threads. Block b covers 32 points; each point
// gets 8 slice-threads, each summing NCHUNKS/8 = 32 chunk rows (coalesced), then
// an smem tree folds the 8 slices.
#define RED_THREADS 256
#define PTS_PER_RBLOCK 32
#define SLICES 8

__global__ void __launch_bounds__(RED_THREADS)
metadyn_reduce(float* __restrict__ out)
{
    __shared__ float s_red[SLICES][PTS_PER_RBLOCK];
    const int lane_p = threadIdx.x & (PTS_PER_RBLOCK - 1);   // point within block
    const int slice  = threadIdx.x >> 5;                      // 0..7
    const int p = blockIdx.x * PTS_PER_RBLOCK + lane_p;

    float s = 0.f;
    #pragma unroll 8
    for (int c = slice; c < NCHUNKS; c += SLICES) {
        s += g_part[c * N_POINTS + p];
    }
    s_red[slice][lane_p] = s;
    __syncthreads();

    if (threadIdx.x < PTS_PER_RBLOCK) {
        float t0 = s_red[0][lane_p] + s_red[1][lane_p];
        float t1 = s_red[2][lane_p] + s_red[3][lane_p];
        float t2 = s_red[4][lane_p] + s_red[5][lane_p];
        float t3 = s_red[6][lane_p] + s_red[7][lane_p];
        out[p] = (t0 + t1) + (t2 + t3);
    }
}

extern "C" void kernel_launch(void* const* d_in, const int* in_sizes, int n_in,
                              void* d_out, int out_size)
{
    const float* col = (const float*)d_in[0];
    const float* cen = (const float*)d_in[1];
    const float* wdt = (const float*)d_in[2];
    const float* hgt = (const float*)d_in[3];
    float* out = (float*)d_out;

    dim3 grid(PTILES, NCHUNKS);
    metadyn_main<<<grid, THREADS>>>(col, cen, wdt, hgt);
    metadyn_reduce<<<N_POINTS / PTS_PER_RBLOCK, RED_THREADS>>>(out);
}